// round 16
// baseline (speedup 1.0000x reference)
#include <cuda_runtime.h>
#include <cuda_bf16.h>

#define R2C 0.70710678118654752f

__device__ __forceinline__ float soft05(float x) {
    return copysignf(fmaxf(fabsf(x) - 0.05f, 0.0f), x);
}

// x[8] -> o[8] = {RE0,RE1,RE2,RE3,RE4,SI1,SI2,SI3}, unnormalized.
__device__ __forceinline__ void dft8_real(const float* x, float* o) {
    float s04 = x[0] + x[4], d04 = x[0] - x[4];
    float s26 = x[2] + x[6], d26 = x[2] - x[6];
    float s15 = x[1] + x[5], d15 = x[1] - x[5];
    float s37 = x[3] + x[7], d37 = x[3] - x[7];
    float t1 = s04 + s26, t2 = s15 + s37;
    o[0] = t1 + t2; o[4] = t1 - t2; o[2] = s04 - s26;
    float u = d15 - d37, v = d15 + d37;
    o[1] = fmaf(R2C, u, d04); o[3] = fmaf(-R2C, u, d04);
    o[5] = fmaf(R2C, v, d26);
    o[6] = s15 - s37;
    o[7] = fmaf(R2C, v, -d26);
}

// o[u] = cosDFT_u(q) - sinDFT_u(w), raw/unscaled.
__device__ __forceinline__ void dft8_combine(const float* q, const float* w, float* o) {
    float s04 = q[0] + q[4], d04 = q[0] - q[4];
    float s26 = q[2] + q[6];
    float s15 = q[1] + q[5], d15 = q[1] - q[5];
    float s37 = q[3] + q[7], d37 = q[3] - q[7];
    float t1 = s04 + s26, t2 = s15 + s37;
    float RE0 = t1 + t2, RE4 = t1 - t2, RE2 = s04 - s26;
    float uq = d15 - d37;
    float RE1 = fmaf(R2C, uq, d04), RE3 = fmaf(-R2C, uq, d04);
    float d26w = w[2] - w[6];
    float vw = (w[1] - w[5]) + (w[3] - w[7]);
    float SI1 = fmaf(R2C, vw, d26w);
    float SI2 = (w[1] + w[5]) - (w[3] + w[7]);
    float SI3 = fmaf(R2C, vw, -d26w);
    o[0] = RE0;        o[4] = RE4;
    o[1] = RE1 - SI1;  o[7] = RE1 + SI1;
    o[2] = RE2 - SI2;  o[6] = RE2 + SI2;
    o[3] = RE3 - SI3;  o[5] = RE3 + SI3;
}

// o[u] = cosDFT_u(q) only (for lines with zero sine part).
__device__ __forceinline__ void dft8_cos(const float* q, float* o) {
    float s04 = q[0] + q[4], d04 = q[0] - q[4];
    float s26 = q[2] + q[6];
    float s15 = q[1] + q[5], d15 = q[1] - q[5];
    float s37 = q[3] + q[7], d37 = q[3] - q[7];
    float t1 = s04 + s26, t2 = s15 + s37;
    o[0] = t1 + t2; o[4] = t1 - t2;
    o[2] = s04 - s26; o[6] = o[2];
    float uq = d15 - d37;
    o[1] = fmaf(R2C, uq, d04); o[3] = fmaf(-R2C, uq, d04);
    o[5] = o[3]; o[7] = o[1];
}

// Dual conjugate lines: CR = cosDFT(q), SW = sinDFT(w).
// oA[u] = CR[u] - SW[u] (line tau), oB[u] = CR[u] + SW[u] (line 8-tau).
__device__ __forceinline__ void dft8_dual(const float* q, const float* w,
                                          float* oA, float* oB) {
    float s04 = q[0] + q[4], d04 = q[0] - q[4];
    float s26 = q[2] + q[6];
    float s15 = q[1] + q[5], d15 = q[1] - q[5];
    float s37 = q[3] + q[7], d37 = q[3] - q[7];
    float t1 = s04 + s26, t2 = s15 + s37;
    float CR0 = t1 + t2, CR4 = t1 - t2, CR2 = s04 - s26;
    float uq = d15 - d37;
    float CR1 = fmaf(R2C, uq, d04), CR3 = fmaf(-R2C, uq, d04);
    float d26w = w[2] - w[6];
    float vw = (w[1] - w[5]) + (w[3] - w[7]);
    float SW1 = fmaf(R2C, vw, d26w);
    float SW2 = (w[1] + w[5]) - (w[3] + w[7]);
    float SW3 = fmaf(R2C, vw, -d26w);
    oA[0] = CR0;        oB[0] = CR0;
    oA[4] = CR4;        oB[4] = CR4;
    oA[1] = CR1 - SW1;  oB[1] = CR1 + SW1;
    oA[2] = CR2 - SW2;  oB[2] = CR2 + SW2;
    oA[3] = CR3 - SW3;  oB[3] = CR3 + SW3;
    oA[5] = CR3 + SW3;  oB[5] = CR3 - SW3;
    oA[6] = CR2 + SW2;  oB[6] = CR2 - SW2;
    oA[7] = CR1 + SW1;  oB[7] = CR1 - SW1;
}

// Inverse combine for row pair (C0, C0+1), INTERLEAVED layout:
// element e of this block lives at bb[e * 32]. Line k slot s -> e = k*8+s.
template<int C0>
__device__ __forceinline__ void combine_pair(const float* __restrict__ bb,
                                             float* oA, float* oB) {
    constexpr int JP[8]  = {0, 1, 2, 3, 4, 3, 2, 1};
    constexpr int IXt[8] = {0, 5, 6, 7, 0, 7, 6, 5};
    constexpr float SGt[8] = {0.f, 1.f, 1.f, 1.f, 0.f, -1.f, -1.f, -1.f};

    float q[8];
    #pragma unroll
    for (int k = 0; k < 8; k++) q[k] = bb[(k * 8 + JP[C0]) * 32];
    if constexpr (SGt[C0] == 0.f) {
        dft8_cos(q, oA);
    } else {
        float w[8];
        #pragma unroll
        for (int k = 0; k < 8; k++) w[k] = SGt[C0] * bb[(k * 8 + IXt[C0]) * 32];
        dft8_combine(q, w, oA);
    }
    float q2[8], w2[8];
    #pragma unroll
    for (int k = 0; k < 8; k++) {
        q2[k] = bb[(k * 8 + JP[C0 + 1]) * 32];
        w2[k] = SGt[C0 + 1] * bb[(k * 8 + IXt[C0 + 1]) * 32];
    }
    dft8_combine(q2, w2, oB);
}

// Haar refine for a row pair (fully thread-local).
__device__ __forceinline__ void haar_pair(const float* e, const float* o,
                                          float* re, float* ro) {
    #pragma unroll
    for (int m = 0; m < 4; m++) {
        float a = e[2*m], b = e[2*m+1], c = o[2*m], d = o[2*m+1];
        float u0 = a + b, v0 = a - b, u1 = c + d, v1 = c - d;
        float LL = (u0 + u1) * 0.5f;
        float LH = soft05((u0 - u1) * 0.5f);
        float HL = soft05((v0 + v1) * 0.5f);
        float HH = soft05((v0 - v1) * 0.5f);
        float p  = LL + LH, qd = HL + HH;
        float rr = LL - LH, sd = HL - HH;
        re[2*m]   = 0.5f * (p + qd);
        re[2*m+1] = 0.5f * (p - qd);
        ro[2*m]   = 0.5f * (rr + sd);
        ro[2*m+1] = 0.5f * (rr - sd);
    }
}

__device__ __forceinline__ void nonlin8(float* c) {
    #pragma unroll
    for (int i = 0; i < 8; i++) {
        float v = c[i] * 0.125f;                 // fold ortho 1/8
        float m = fminf(fabsf(v) * 0.4f, 1.0f);  // shrink below 2.5
        v *= m;
        c[i] = fminf(fmaxf(v, -10.0f), 10.0f);   // clip
    }
}

// Vertical 3-tap blur for two consecutive rows from INTERLEAVED panel:
// hp[j * 8] = f4 element j (j=0 is row R0-1 first half). Conflict-free.
__device__ __forceinline__ void vblur2(const float4* __restrict__ hp,
                                       float w0, float w1,
                                       float* g0, float* g1) {
    #pragma unroll
    for (int h = 0; h < 2; h++) {
        float4 A = hp[h * 8], B = hp[(2 + h) * 8];
        float4 C = hp[(4 + h) * 8], D = hp[(6 + h) * 8];
        g0[4*h+0] = fmaf(w1, A.x + C.x, w0 * B.x);
        g0[4*h+1] = fmaf(w1, A.y + C.y, w0 * B.y);
        g0[4*h+2] = fmaf(w1, A.z + C.z, w0 * B.z);
        g0[4*h+3] = fmaf(w1, A.w + C.w, w0 * B.w);
        g1[4*h+0] = fmaf(w1, B.x + D.x, w0 * C.x);
        g1[4*h+1] = fmaf(w1, B.y + D.y, w0 * C.y);
        g1[4*h+2] = fmaf(w1, B.z + D.z, w0 * C.z);
        g1[4*h+3] = fmaf(w1, B.w + D.w, w0 * C.w);
    }
}

// CTA = 64x32 px, 128 threads, smem 16.9KB -> TARGET 13 CTAs/SM (regs<=39).
// INTERLEAVED smem: panel f4 (i, bcol) at gpan4[i*8+bcol] (i = 2*row+h,
// 68 per column); bufF element (e, blk) at bufF[e*32+blk] (e = line*8+slot).
// Bank = blk (all 32 distinct) -> every transform LDS/STS conflict-free.
// Thread: blk = t&31 (bcol=blk&7, brow=blk>>3), r2 = t>>5 (warp-uniform)
// -> owns block rows 2r2,2r2+1; forward column stage owns conjugate
// columns {r2, 8-r2} ({0,4} for r2=0).
__global__ __launch_bounds__(128, 13) void sas_fusedE_kernel(
    const float* __restrict__ in, float* __restrict__ out)
{
    __shared__ __align__(16) float4 gpan4[544];   // hblur panels (8704 B)
    __shared__ __align__(16) float bufF[2048];    // transpose buf (8192 B)

    const int t = threadIdx.x;
    const int tileX = blockIdx.x * 64;
    const int tileY = blockIdx.y * 32;
    const int z = blockIdx.z;
    const float* img = in + (size_t)z * (512 * 512);

    const float e1 = expf(-0.78125f);            // exp(-1/(2*0.8^2))
    const float w0 = 1.0f / (1.0f + 2.0f * e1);
    const float w1 = e1 * w0;

    // ---- Loader: horizontal blur, global -> interleaved panels ----
    for (int s = t; s < 544; s += 128) {         // 34 rows x 16 f4
        int row = s >> 4, f4c = s & 15;
        int gy = tileY + row - 1;
        gy = (gy < 0) ? -gy : ((gy > 511) ? 1022 - gy : gy);
        const float* rp = img + (size_t)gy * 512;
        int base = tileX + f4c * 4;
        float4 A = *(const float4*)(rp + base);
        float lv = __shfl_up_sync(0xffffffffu, A.w, 1);
        float rv = __shfl_down_sync(0xffffffffu, A.x, 1);
        if (f4c == 0)  lv = (base == 0)   ? A.y : rp[base - 1];
        if (f4c == 15) rv = (base == 508) ? A.z : rp[base + 4];
        float4 o;
        o.x = fmaf(w1, lv  + A.y, w0 * A.x);
        o.y = fmaf(w1, A.x + A.z, w0 * A.y);
        o.z = fmaf(w1, A.y + A.w, w0 * A.z);
        o.w = fmaf(w1, A.z + rv,  w0 * A.w);
        gpan4[(2 * row + (f4c & 1)) * 8 + (f4c >> 1)] = o;
    }
    __syncthreads();

    const int r2 = t >> 5;                       // warp-uniform
    const int blk = t & 31;
    const int bcol = blk & 7;
    const int brow = blk >> 3;
    const int R0 = brow * 8 + 2 * r2;            // strip-local row 0..30
    const float4* hp = gpan4 + 2 * R0 * 8 + bcol;    // element j at hp[j*8]
    float* fb = bufF + blk;                      // element e at fb[e*32]

    // ---- Vertical blur (2 rows) + row DFT -> bufF (g NOT kept live) ----
    {
        float g0[8], g1[8];
        vblur2(hp, w0, w1, g0, g1);
        float ta[8], tb[8];
        dft8_real(g0, ta);
        dft8_real(g1, tb);
        #pragma unroll
        for (int s = 0; s < 8; s++) fb[((2 * r2) * 8 + s) * 32] = ta[s];
        #pragma unroll
        for (int s = 0; s < 8; s++) fb[((2 * r2 + 1) * 8 + s) * 32] = tb[s];
    }
    __syncthreads();

    // ---- Forward column stage: conjugate pair {tau, 8-tau} in one pass ----
    float sA[8], sB[8];
    int c2;                                      // second column index
    {
        float q[8], w[8];
        #pragma unroll
        for (int k = 0; k < 8; k++) {
            q[k] = fb[(k * 8 + r2) * 32];        // slot tau   (RE_tau)
            w[k] = fb[(k * 8 + 4 + r2) * 32];    // slot tau+4 (SI_tau / RE4)
        }
        float cA[8], cB[8];
        if (r2 == 0) {                           // cols 0 and 4: cos-only
            dft8_cos(q, cA);
            dft8_cos(w, cB);                     // w holds slot 4 = RE4
            c2 = 4;
        } else {                                 // cols tau and 8-tau
            dft8_dual(q, w, cA, cB);
            c2 = 8 - r2;
        }
        nonlin8(cA);
        nonlin8(cB);
        dft8_real(cA, sA);
        dft8_real(cB, sB);
    }
    __syncthreads();                             // all bufF reads complete
    #pragma unroll
    for (int s = 0; s < 8; s++) fb[(r2 * 8 + s) * 32] = sA[s];
    #pragma unroll
    for (int s = 0; s < 8; s++) fb[(c2 * 8 + s) * 32] = sB[s];
    __syncthreads();

    // ---- Inverse row combine (rows 2r2, 2r2+1) ----
    float idA[8], idB[8];
    switch (r2) {
        case 0: combine_pair<0>(fb, idA, idB); break;
        case 1: combine_pair<2>(fb, idA, idB); break;
        case 2: combine_pair<4>(fb, idA, idB); break;
        default: combine_pair<6>(fb, idA, idB); break;
    }
    #pragma unroll
    for (int x = 0; x < 8; x++) { idA[x] *= 0.125f; idB[x] *= 0.125f; }

    const int bidx = z / 3;
    const int cch = z - bidx * 3;
    const size_t obase =
        ((size_t)(bidx * 6 + cch) * 512 + (tileY + R0)) * 512 + tileX + bcol * 8;

    // ---- I-branch: haar + store ----
    {
        float oa[8], ob[8];
        haar_pair(idA, idB, oa, ob);
        float4* p0 = (float4*)(out + obase);
        p0[0] = make_float4(oa[0], oa[1], oa[2], oa[3]);
        p0[1] = make_float4(oa[4], oa[5], oa[6], oa[7]);
        float4* p1 = (float4*)(out + obase + 512);
        p1[0] = make_float4(ob[0], ob[1], ob[2], ob[3]);
        p1[1] = make_float4(ob[4], ob[5], ob[6], ob[7]);
    }

    // ---- R-branch: recompute blur from persistent panels, residual, haar ----
    {
        float rdA[8], rdB[8];
        vblur2(hp, w0, w1, rdA, rdB);            // rd = g (then subtract id)
        #pragma unroll
        for (int x = 0; x < 8; x++) { rdA[x] -= idA[x]; rdB[x] -= idB[x]; }
        float oa[8], ob[8];
        haar_pair(rdA, rdB, oa, ob);
        const size_t rbase = obase + (size_t)3 * 512 * 512;
        float4* p0 = (float4*)(out + rbase);
        p0[0] = make_float4(oa[0], oa[1], oa[2], oa[3]);
        p0[1] = make_float4(oa[4], oa[5], oa[6], oa[7]);
        float4* p1 = (float4*)(out + rbase + 512);
        p1[0] = make_float4(ob[0], ob[1], ob[2], ob[3]);
        p1[1] = make_float4(ob[4], ob[5], ob[6], ob[7]);
    }
}

extern "C" void kernel_launch(void* const* d_in, const int* in_sizes, int n_in,
                              void* d_out, int out_size) {
    const float* I = (const float*)d_in[0];
    float* out = (float*)d_out;
    dim3 block(128);
    dim3 grid(8, 16, 96);
    sas_fusedE_kernel<<<grid, block>>>(I, out);
}

// round 17
// speedup vs baseline: 1.0295x; 1.0295x over previous
#include <cuda_runtime.h>
#include <cuda_bf16.h>

#define R2C 0.70710678118654752f

__device__ __forceinline__ float soft05(float x) {
    return copysignf(fmaxf(fabsf(x) - 0.05f, 0.0f), x);
}

// x[8] -> o[8] = {RE0,RE1,RE2,RE3,RE4,SI1,SI2,SI3}, unnormalized.
__device__ __forceinline__ void dft8_real(const float* x, float* o) {
    float s04 = x[0] + x[4], d04 = x[0] - x[4];
    float s26 = x[2] + x[6], d26 = x[2] - x[6];
    float s15 = x[1] + x[5], d15 = x[1] - x[5];
    float s37 = x[3] + x[7], d37 = x[3] - x[7];
    float t1 = s04 + s26, t2 = s15 + s37;
    o[0] = t1 + t2; o[4] = t1 - t2; o[2] = s04 - s26;
    float u = d15 - d37, v = d15 + d37;
    o[1] = fmaf(R2C, u, d04); o[3] = fmaf(-R2C, u, d04);
    o[5] = fmaf(R2C, v, d26);
    o[6] = s15 - s37;
    o[7] = fmaf(R2C, v, -d26);
}

// o[u] = cosDFT_u(q) only (for lines with zero sine part).
__device__ __forceinline__ void dft8_cos(const float* q, float* o) {
    float s04 = q[0] + q[4], d04 = q[0] - q[4];
    float s26 = q[2] + q[6];
    float s15 = q[1] + q[5], d15 = q[1] - q[5];
    float s37 = q[3] + q[7], d37 = q[3] - q[7];
    float t1 = s04 + s26, t2 = s15 + s37;
    o[0] = t1 + t2; o[4] = t1 - t2;
    o[2] = s04 - s26; o[6] = o[2];
    float uq = d15 - d37;
    o[1] = fmaf(R2C, uq, d04); o[3] = fmaf(-R2C, uq, d04);
    o[5] = o[3]; o[7] = o[1];
}

// Dual conjugate lines: CR = cosDFT(q), SW = sinDFT(w).
// oA[u] = CR[u] - SW[u] (line tau), oB[u] = CR[u] + SW[u] (line 8-tau).
__device__ __forceinline__ void dft8_dual(const float* q, const float* w,
                                          float* oA, float* oB) {
    float s04 = q[0] + q[4], d04 = q[0] - q[4];
    float s26 = q[2] + q[6];
    float s15 = q[1] + q[5], d15 = q[1] - q[5];
    float s37 = q[3] + q[7], d37 = q[3] - q[7];
    float t1 = s04 + s26, t2 = s15 + s37;
    float CR0 = t1 + t2, CR4 = t1 - t2, CR2 = s04 - s26;
    float uq = d15 - d37;
    float CR1 = fmaf(R2C, uq, d04), CR3 = fmaf(-R2C, uq, d04);
    float d26w = w[2] - w[6];
    float vw = (w[1] - w[5]) + (w[3] - w[7]);
    float SW1 = fmaf(R2C, vw, d26w);
    float SW2 = (w[1] + w[5]) - (w[3] + w[7]);
    float SW3 = fmaf(R2C, vw, -d26w);
    oA[0] = CR0;        oB[0] = CR0;
    oA[4] = CR4;        oB[4] = CR4;
    oA[1] = CR1 - SW1;  oB[1] = CR1 + SW1;
    oA[2] = CR2 - SW2;  oB[2] = CR2 + SW2;
    oA[3] = CR3 - SW3;  oB[3] = CR3 + SW3;
    oA[5] = CR3 + SW3;  oB[5] = CR3 - SW3;
    oA[6] = CR2 + SW2;  oB[6] = CR2 - SW2;
    oA[7] = CR1 + SW1;  oB[7] = CR1 - SW1;
}

// Haar refine for a row pair (fully thread-local).
__device__ __forceinline__ void haar_pair(const float* e, const float* o,
                                          float* re, float* ro) {
    #pragma unroll
    for (int m = 0; m < 4; m++) {
        float a = e[2*m], b = e[2*m+1], c = o[2*m], d = o[2*m+1];
        float u0 = a + b, v0 = a - b, u1 = c + d, v1 = c - d;
        float LL = (u0 + u1) * 0.5f;
        float LH = soft05((u0 - u1) * 0.5f);
        float HL = soft05((v0 + v1) * 0.5f);
        float HH = soft05((v0 - v1) * 0.5f);
        float p  = LL + LH, qd = HL + HH;
        float rr = LL - LH, sd = HL - HH;
        re[2*m]   = 0.5f * (p + qd);
        re[2*m+1] = 0.5f * (p - qd);
        ro[2*m]   = 0.5f * (rr + sd);
        ro[2*m+1] = 0.5f * (rr - sd);
    }
}

__device__ __forceinline__ void nonlin8(float* c) {
    #pragma unroll
    for (int i = 0; i < 8; i++) {
        float v = c[i] * 0.125f;                 // fold ortho 1/8
        float m = fminf(fabsf(v) * 0.4f, 1.0f);  // shrink below 2.5
        v *= m;
        c[i] = fminf(fmaxf(v, -10.0f), 10.0f);   // clip
    }
}

// Vertical 3-tap blur for two consecutive rows, half-split to bound liveness.
__device__ __forceinline__ void vblur2(const float4* __restrict__ hp,
                                       float w0, float w1,
                                       float* g0, float* g1) {
    #pragma unroll
    for (int h = 0; h < 2; h++) {
        float4 A = hp[h], B = hp[2 + h], C = hp[4 + h], D = hp[6 + h];
        g0[4*h+0] = fmaf(w1, A.x + C.x, w0 * B.x);
        g0[4*h+1] = fmaf(w1, A.y + C.y, w0 * B.y);
        g0[4*h+2] = fmaf(w1, A.z + C.z, w0 * B.z);
        g0[4*h+3] = fmaf(w1, A.w + C.w, w0 * B.w);
        g1[4*h+0] = fmaf(w1, B.x + D.x, w0 * C.x);
        g1[4*h+1] = fmaf(w1, B.y + D.y, w0 * C.y);
        g1[4*h+2] = fmaf(w1, B.z + D.z, w0 * C.z);
        g1[4*h+3] = fmaf(w1, B.w + D.w, w0 * C.w);
    }
}

#define PSTR 276   // panel stride floats; 69 odd -> f4 phase conflict-free
#define WBUF 544   // per-warp transpose region (4 x 136 floats)

// CTA = 64x32 px, 128 threads, smem 17.1KB, 12 CTAs/SM (regs <= 40).
// Warp w owns block-row w (8 blocks). lane: b = lane&7 (bcol), p = lane>>3.
// Transpose buffer is WARP-PRIVATE: element (line L, slot s, blk b) at
// region(L)*136 + half(L)*64 + s*8 + b; lines: region=L>>1 half=L&1;
// cols: region=c&3 half=c>>2. All accesses bank = 8*const + 8p + b ->
// conflict-free. Only ONE __syncthreads (post-loader); 3 __syncwarp.
__global__ __launch_bounds__(128, 12) void sas_fusedF_kernel(
    const float* __restrict__ in, float* __restrict__ out)
{
    __shared__ __align__(16) float smemA[8 * PSTR];   // hblur panels, persist
    __shared__ __align__(16) float bufW[4 * WBUF];    // warp-private buffers

    const int t = threadIdx.x;
    const int tileX = blockIdx.x * 64;
    const int tileY = blockIdx.y * 32;
    const int z = blockIdx.z;
    const float* img = in + (size_t)z * (512 * 512);

    const float e1 = expf(-0.78125f);            // exp(-1/(2*0.8^2))
    const float w0 = 1.0f / (1.0f + 2.0f * e1);
    const float w1 = e1 * w0;

    // ---- Loader: horizontal blur, global -> smem panels (34 rows) ----
    for (int s = t; s < 544; s += 128) {         // 34 rows x 16 f4
        int row = s >> 4, f4c = s & 15;
        int gy = tileY + row - 1;
        gy = (gy < 0) ? -gy : ((gy > 511) ? 1022 - gy : gy);
        const float* rp = img + (size_t)gy * 512;
        int base = tileX + f4c * 4;
        float4 A = *(const float4*)(rp + base);
        float lv = __shfl_up_sync(0xffffffffu, A.w, 1);
        float rv = __shfl_down_sync(0xffffffffu, A.x, 1);
        if (f4c == 0)  lv = (base == 0)   ? A.y : rp[base - 1];
        if (f4c == 15) rv = (base == 508) ? A.z : rp[base + 4];
        float4 o;
        o.x = fmaf(w1, lv  + A.y, w0 * A.x);
        o.y = fmaf(w1, A.x + A.z, w0 * A.y);
        o.z = fmaf(w1, A.y + A.w, w0 * A.z);
        o.w = fmaf(w1, A.z + rv,  w0 * A.w);
        *(float4*)(smemA + (f4c >> 1) * PSTR + row * 8 + (f4c & 1) * 4) = o;
    }
    __syncthreads();                             // ONLY CTA barrier

    const int w = t >> 5;                        // warp = block-row
    const int lane = t & 31;
    const int b = lane & 7;                      // bcol
    const int p = lane >> 3;                     // row-pair / quad index
    const int hi1 = p & 1;
    const float* panel = smemA + b * PSTR;
    float* fbase = bufW + w * WBUF + b;          // + region*136 + half*64 + s*8

    // ---- Vertical blur rows 2p,2p+1 of block (b,w) + row DFT -> buffer ----
    {
        const float4* hp = (const float4*)(panel + (8 * w + 2 * p) * 8);
        float g0[8], g1[8];
        vblur2(hp, w0, w1, g0, g1);
        float ta[8], tb[8];
        dft8_real(g0, ta);
        dft8_real(g1, tb);
        float* fw = fbase + p * 136;             // lines 2p (half0), 2p+1
        #pragma unroll
        for (int s = 0; s < 8; s++) fw[s * 8] = ta[s];
        #pragma unroll
        for (int s = 0; s < 8; s++) fw[64 + s * 8] = tb[s];
    }
    __syncwarp();

    // ---- Forward column stage: conjugate pair {p, 8-p} ({0,4} for p=0) ----
    float sA[8], sB[8];
    {
        float q[8], ww[8];
        #pragma unroll
        for (int k = 0; k < 8; k++) {
            const float* fr = fbase + (k >> 1) * 136 + (k & 1) * 64 + p * 8;
            q[k]  = fr[0];                       // line k slot p
            ww[k] = fr[32];                      // line k slot p+4
        }
        float cA[8], cB[8];
        if (p == 0) {                            // cols 0 and 4: cos-only
            dft8_cos(q, cA);
            dft8_cos(ww, cB);
        } else {                                 // cols p and 8-p
            dft8_dual(q, ww, cA, cB);
        }
        nonlin8(cA);
        nonlin8(cB);
        dft8_real(cA, sA);
        dft8_real(cB, sB);
    }
    __syncwarp();                                // line reads done (WAR)
    {
        const int c2 = (p == 0) ? 4 : 8 - p;
        float* fw1 = fbase + p * 136;            // col p: region p, half 0
        float* fw2 = fbase + (c2 & 3) * 136 + 64;    // col c2: half 1
        #pragma unroll
        for (int s = 0; s < 8; s++) fw1[s * 8] = sA[s];
        #pragma unroll
        for (int s = 0; s < 8; s++) fw2[s * 8] = sB[s];
    }
    __syncwarp();

    // ---- Inverse row dual: rows p and 8-p (p=0: rows 0 and 4) ----
    float idA[8], idB[8];
    {
        float q[8], ww[8];
        #pragma unroll
        for (int c = 0; c < 8; c++) {
            const float* fr = fbase + (c & 3) * 136 + (c >> 2) * 64 + p * 8;
            q[c]  = fr[0];                       // col c slot p
            ww[c] = fr[32];                      // col c slot p+4
        }
        if (p == 0) {
            dft8_cos(q, idA);                    // row 0
            dft8_cos(ww, idB);                   // row 4
        } else {
            dft8_dual(q, ww, idA, idB);          // rows p, 8-p
        }
        #pragma unroll
        for (int x = 0; x < 8; x++) { idA[x] *= 0.125f; idB[x] *= 0.125f; }
    }

    // ---- Re-pair rows for Haar IN PLACE: rotation shfl. After this,
    //      idA = even row of pair, idB = odd row. ----
    {
        const int src = b + 8 * ((p + 1) & 3);
        #pragma unroll
        for (int x = 0; x < 8; x++) {
            float snd = hi1 ? idA[x] : idB[x];
            float rcv = __shfl_sync(0xffffffffu, snd, src);
            if (hi1) idA[x] = rcv; else idB[x] = rcv;
        }
    }
    const int rl = hi1 ? (7 - p) : p;            // even row of my pair
    const int Rg = 8 * w + rl;                   // strip-local even row

    const int bidx = z / 3;
    const int cch = z - bidx * 3;
    const size_t obase =
        ((size_t)(bidx * 6 + cch) * 512 + (tileY + Rg)) * 512 + tileX + b * 8;

    // ---- I-branch: haar + store ----
    {
        float oa[8], ob[8];
        haar_pair(idA, idB, oa, ob);
        float4* q0 = (float4*)(out + obase);
        q0[0] = make_float4(oa[0], oa[1], oa[2], oa[3]);
        q0[1] = make_float4(oa[4], oa[5], oa[6], oa[7]);
        float4* q1 = (float4*)(out + obase + 512);
        q1[0] = make_float4(ob[0], ob[1], ob[2], ob[3]);
        q1[1] = make_float4(ob[4], ob[5], ob[6], ob[7]);
    }

    // ---- R-branch: recompute blur rows Rg, Rg+1, residual, haar, store ----
    {
        const float4* hp2 = (const float4*)(panel + Rg * 8);
        float rdA[8], rdB[8];
        vblur2(hp2, w0, w1, rdA, rdB);           // g rows Rg, Rg+1
        #pragma unroll
        for (int x = 0; x < 8; x++) { rdA[x] -= idA[x]; rdB[x] -= idB[x]; }
        float oa[8], ob[8];
        haar_pair(rdA, rdB, oa, ob);
        const size_t rbase = obase + (size_t)3 * 512 * 512;
        float4* q0 = (float4*)(out + rbase);
        q0[0] = make_float4(oa[0], oa[1], oa[2], oa[3]);
        q0[1] = make_float4(oa[4], oa[5], oa[6], oa[7]);
        float4* q1 = (float4*)(out + rbase + 512);
        q1[0] = make_float4(ob[0], ob[1], ob[2], ob[3]);
        q1[1] = make_float4(ob[4], ob[5], ob[6], ob[7]);
    }
}

extern "C" void kernel_launch(void* const* d_in, const int* in_sizes, int n_in,
                              void* d_out, int out_size) {
    const float* I = (const float*)d_in[0];
    float* out = (float*)d_out;
    dim3 block(128);
    dim3 grid(8, 16, 96);
    sas_fusedF_kernel<<<grid, block>>>(I, out);
}